// round 15
// baseline (speedup 1.0000x reference)
#include <cuda_runtime.h>
#include <cstdint>

#define TPB 256
#define GPB 256  // graphs per block (== TPB, 1 thread per graph)

// Folded constants: v[4][16] (only k<14 used), s[4] @64..67, C @68
__device__ __align__(16) float g_const[80];
// Precompute scratch
__device__ __align__(16) float g_t1[256];
__device__ __align__(16) float g_t2[256];
__device__ __align__(16) float g_Ms[256];
__device__ __align__(16) float g_us[512];
// Grid-sync counters (reset at end of each precompute launch -> deterministic)
__device__ int g_syncc[4];

// ---------------------------------------------------------------------------
// Fused precompute: ONE kernel, 32 blocks x 256 threads, internal grid syncs.
//   S1: t1 = Wl3 @ w4          (all 32 blocks, 8 rows each)     sync0 (32)
//   S2: t2 = Wl2 @ t1          (all 32)                          sync1 (32)
//   S3: Ms = Wl1(t2+w4) + w4   (all 32)                          sync2 (arrive 32; only b<8 spin)
//   S4: u_n = W2 m_n           (blocks 0-7)                      sync3 (arrive 8; only b==0 spins)
//   S5: v[n][k], s[n], C       (block 0)                         reset counters
// Deadlock-free: 32 blocks co-resident (<<148 SMs); arrive-without-spin for
// exiting blocks; reset only after all possible spinners have passed.
// ---------------------------------------------------------------------------
__device__ __forceinline__ float dot256(const float4* wr, const float* vsm,
                                        int lane)
{
    float a = 0.f;
    #pragma unroll
    for (int i = 0; i < 2; ++i) {
        float4 w = wr[lane + 32 * i];
        int c = 4 * (lane + 32 * i);
        a = fmaf(w.x, vsm[c+0], fmaf(w.y, vsm[c+1],
            fmaf(w.z, vsm[c+2], fmaf(w.w, vsm[c+3], a))));
    }
    return a;
}

__global__ void __launch_bounds__(256) precompute_fused(
    const float* __restrict__ W1,  const float* __restrict__ b1,
    const float* __restrict__ W2,  const float* __restrict__ b2,
    const float* __restrict__ Wl1, const float* __restrict__ bl1,
    const float* __restrict__ Wl2, const float* __restrict__ bl2,
    const float* __restrict__ Wl3, const float* __restrict__ bl3,
    const float* __restrict__ Wl4, const float* __restrict__ bl4)
{
    __shared__ float w4s[256];
    __shared__ float tbuf[256];
    __shared__ __align__(16) float W2s[64 * 17 * 4];  // 17408 B (stage 4)
    __shared__ __align__(16) float msbuf[64];
    __shared__ float part[256];
    __shared__ __align__(16) float us_s[512];

    const int t = threadIdx.x;
    const int b = blockIdx.x;
    const int row = b * 8 + (t >> 5);
    const int lane = t & 31;

    // ---- Stage 1: t1 = Wl3 @ w4 ----
    w4s[t] = Wl4[t];
    __syncthreads();
    {
        float a = dot256((const float4*)(Wl3 + row * 256), w4s, lane);
        #pragma unroll
        for (int o = 16; o; o >>= 1) a += __shfl_xor_sync(0xFFFFFFFFu, a, o);
        if (lane == 0) g_t1[row] = a;
    }
    __syncthreads();
    if (t == 0) {
        __threadfence(); atomicAdd(&g_syncc[0], 1);
        while (atomicAdd(&g_syncc[0], 0) < 32) {}
        __threadfence();
    }
    __syncthreads();

    // ---- Stage 2: t2 = Wl2 @ t1 ----
    tbuf[t] = g_t1[t];
    __syncthreads();
    {
        float a = dot256((const float4*)(Wl2 + row * 256), tbuf, lane);
        #pragma unroll
        for (int o = 16; o; o >>= 1) a += __shfl_xor_sync(0xFFFFFFFFu, a, o);
        if (lane == 0) g_t2[row] = a;
    }
    __syncthreads();
    if (t == 0) {
        __threadfence(); atomicAdd(&g_syncc[1], 1);
        while (atomicAdd(&g_syncc[1], 0) < 32) {}
        __threadfence();
    }
    __syncthreads();

    // ---- Stage 3: Ms = Wl1 @ t2 + Wl1 @ w4 + w4 (single pass) ----
    tbuf[t] = g_t2[t];
    __syncthreads();
    {
        const float4* wr = (const float4*)(Wl1 + row * 256);
        float a1 = 0.f, a2 = 0.f;
        #pragma unroll
        for (int i = 0; i < 2; ++i) {
            float4 w = wr[lane + 32 * i];
            int c = 4 * (lane + 32 * i);
            a1 = fmaf(w.x, tbuf[c+0], fmaf(w.y, tbuf[c+1],
                 fmaf(w.z, tbuf[c+2], fmaf(w.w, tbuf[c+3], a1))));
            a2 = fmaf(w.x, w4s[c+0], fmaf(w.y, w4s[c+1],
                 fmaf(w.z, w4s[c+2], fmaf(w.w, w4s[c+3], a2))));
        }
        #pragma unroll
        for (int o = 16; o; o >>= 1) {
            a1 += __shfl_xor_sync(0xFFFFFFFFu, a1, o);
            a2 += __shfl_xor_sync(0xFFFFFFFFu, a2, o);
        }
        if (lane == 0) g_Ms[row] = a1 + a2 + w4s[row];
    }
    __syncthreads();
    if (t == 0) { __threadfence(); atomicAdd(&g_syncc[2], 1); }
    if (b >= 8) return;                   // arrive-and-exit, never spin
    if (t == 0) {
        while (atomicAdd(&g_syncc[2], 0) < 32) {}
        __threadfence();
    }
    __syncthreads();

    // ---- Stage 4 (blocks 0-7): u[n][chalf..chalf+63] = W2 rows . m_n ----
    {
        const int n = b >> 1;
        const int chalf = (b & 1) * 64;
        float4* W2s4 = (float4*)W2s;
        const float4* src = ((const float4*)W2) + chalf * 16;
        #pragma unroll
        for (int i2 = 0; i2 < 4; ++i2) {
            int idx = t + 256 * i2;           // 0..1023
            int c = idx >> 4, i = idx & 15;
            W2s4[c * 17 + i] = src[idx];
        }
        if (t < 16) ((float4*)msbuf)[t] = ((const float4*)g_Ms)[n * 16 + t];
        __syncthreads();

        const int q = t >> 6, c = t & 63;
        const float4* ms4 = (const float4*)msbuf;
        float a = 0.f;
        #pragma unroll
        for (int i = 0; i < 4; ++i) {
            float4 w = W2s4[c * 17 + q * 4 + i];
            float4 m = ms4[q * 4 + i];
            a = fmaf(w.x, m.x, fmaf(w.y, m.y, fmaf(w.z, m.z, fmaf(w.w, m.w, a))));
        }
        part[t] = a;
        __syncthreads();
        if (t < 64)
            g_us[n * 128 + chalf + t] =
                part[t] + part[t + 64] + part[t + 128] + part[t + 192];
    }
    __syncthreads();
    if (t == 0) { __threadfence(); atomicAdd(&g_syncc[3], 1); }
    if (b > 0) return;                    // arrive-and-exit
    if (t == 0) {
        while (atomicAdd(&g_syncc[3], 0) < 8) {}
        __threadfence();
    }
    __syncthreads();

    // ---- Stage 5 (block 0): v[n][k], s[n], C ----
    {
        float pc = bl1[t]*g_t2[t] + bl2[t]*g_t1[t]
                 + (bl3[t]+bl1[t])*Wl4[t] + b2[t & 63]*g_Ms[t];
        part[t] = pc;
        us_s[t] = g_us[t];
        us_s[t + 256] = g_us[t + 256];
        __syncthreads();

        if (t < 224) {                    // v[n][k]: 4 threads per output
            int o = t >> 2, q = t & 3;    // o = n*14+k in [0,56)
            int n = o / 14, k = o - 14 * n;
            const float4* wr = (const float4*)(W1 + k * 128);
            const float4* ur = ((const float4*)us_s) + n * 32;
            float a = 0.f;
            #pragma unroll
            for (int i = 0; i < 8; ++i) {
                float4 w = wr[q * 8 + i];
                float4 u = ur[q * 8 + i];
                a = fmaf(w.x, u.x, fmaf(w.y, u.y,
                    fmaf(w.z, u.z, fmaf(w.w, u.w, a))));
            }
            a += __shfl_xor_sync(0xFFFFFFFFu, a, 1);
            a += __shfl_xor_sync(0xFFFFFFFFu, a, 2);
            if (q == 0) g_const[n * 16 + k] = a;
        } else {                          // s_n: 8 threads per n (warp 7)
            int o2 = t - 224;
            int n = o2 >> 3, q = o2 & 7;
            float a = 0.f;
            #pragma unroll
            for (int i = 0; i < 16; ++i)
                a = fmaf(b1[q * 16 + i], us_s[n * 128 + q * 16 + i], a);
            a += __shfl_xor_sync(0xFFFFFFFFu, a, 1);
            a += __shfl_xor_sync(0xFFFFFFFFu, a, 2);
            a += __shfl_xor_sync(0xFFFFFFFFu, a, 4);
            if (q == 0) g_const[64 + n] = a;
        }
        __syncthreads();
        #pragma unroll
        for (int s = 128; s > 0; s >>= 1) {
            if (t < s) part[t] += part[t + s];
            __syncthreads();
        }
        if (t == 0) g_const[68] = part[0] + bl4[0];
    }
    __syncthreads();
    if (t == 0) {                         // reset counters for next replay
        g_syncc[0] = 0; g_syncc[1] = 0; g_syncc[2] = 0; g_syncc[3] = 0;
        __threadfence();
    }
}

// Exactly-rounded 1/sqrt(n) for n = 0..15 (deg in [1,13])
__constant__ float c_rsq[16] = {
    0.0f, 1.0f, 0.70710678118654752f, 0.57735026918962576f,
    0.5f, 0.44721359549995794f, 0.40824829046386302f, 0.37796447300922723f,
    0.35355339059327376f, 0.33333333333333333f, 0.31622776601683794f,
    0.30151134457776363f, 0.28867513459481288f, 0.27735009811261457f,
    0.26726124191242438f, 0.25819888974716110f
};

// ---------------------------------------------------------------------------
// Main kernel (UNCHANGED from the 29.4us version): 1 thread per graph.
// Edges staged + consumed first, then x staged into the SAME smem region
// (union) -> smem 61.8KB -> 3 blocks/SM.
// ---------------------------------------------------------------------------
#define SMEM_CS 61440
#define SMEM_TOTAL 61760

__global__ void __launch_bounds__(TPB, 3) gnn_kernel(
    const float* __restrict__ x, const int* __restrict__ ei,
    float* __restrict__ out)
{
    extern __shared__ unsigned char smem[];
    float4* xs4 = (float4*)smem;
    int4*   es4 = (int4*)smem;
    float*  cs  = (float*)(smem + SMEM_CS);

    const int t = threadIdx.x;
    const long long gbase = (long long)blockIdx.x * GPB;

    if (t < 80) cs[t] = g_const[t];

    const int4* eg = (const int4*)(ei + gbase * 24);
    #pragma unroll
    for (int j0 = 0; j0 < 6; ++j0) {
        int i4 = t + j0 * 256;
        int4 v = eg[i4];
        int g = i4 / 6;
        int j = i4 - g * 6;
        es4[g * 7 + j] = v;
    }
    __syncthreads();

    int me[24];
    #pragma unroll
    for (int j = 0; j < 6; ++j) {
        int4 e = es4[t * 7 + j];
        me[j*4+0] = e.x; me[j*4+1] = e.y; me[j*4+2] = e.z; me[j*4+3] = e.w;
    }
    __syncthreads();   // all edge reads done before x overwrites region0

    const float4* xg = (const float4*)(x + gbase * 56);
    #pragma unroll
    for (int j0 = 0; j0 < 14; ++j0) {
        int i4 = t + j0 * 256;
        float4 v = xg[i4];
        int g = i4 / 14;
        int j = i4 - g * 14;
        xs4[g * 15 + j] = v;
    }

    unsigned long long accm = 0ull;
    #pragma unroll
    for (int e = 0; e < 12; ++e) {
        int s = me[e];
        int d = me[12 + e];
        accm += 1ull << (((d << 2) + s) << 2);
    }

    float dinv[4];
    #pragma unroll
    for (int n = 0; n < 4; ++n) {
        unsigned int rown = (unsigned int)(accm >> (16 * n)) & 0xFFFFu;
        int deg = 1 + (rown & 15) + ((rown >> 4) & 15)
                    + ((rown >> 8) & 15) + ((rown >> 12) & 15);
        dinv[n] = c_rsq[deg];
    }

    float A[16];
    #pragma unroll
    for (int n = 0; n < 4; ++n) {
        #pragma unroll
        for (int m = 0; m < 4; ++m) {
            int cnt = (int)((accm >> (4 * (n * 4 + m))) & 15ull) + (n == m);
            A[n * 4 + m] = dinv[n] * dinv[m] * (float)cnt;
        }
    }

    float acc = cs[68];
    #pragma unroll
    for (int n = 0; n < 4; ++n)
        acc = fmaf(A[n*4] + A[n*4+1] + A[n*4+2] + A[n*4+3], cs[64 + n], acc);

    float A2[16];
    #pragma unroll
    for (int n = 0; n < 4; ++n) {
        #pragma unroll
        for (int m = 0; m < 4; ++m) {
            A2[n*4+m] = fmaf(A[n*4+0], A[0*4+m],
                        fmaf(A[n*4+1], A[1*4+m],
                        fmaf(A[n*4+2], A[2*4+m], A[n*4+3] * A[3*4+m])));
        }
    }

    float g[56];
    #pragma unroll
    for (int e = 0; e < 56; ++e) {
        const int m = e / 14, k = e - 14 * m;
        g[e] = fmaf(A2[0*4+m], cs[0*16+k],
               fmaf(A2[1*4+m], cs[1*16+k],
               fmaf(A2[2*4+m], cs[2*16+k], A2[3*4+m] * cs[3*16+k])));
    }
    __syncthreads();

    #pragma unroll
    for (int j = 0; j < 14; ++j) {
        float4 v = xs4[t * 15 + j];
        const int e = 4 * j;
        acc = fmaf(v.x, g[e+0], fmaf(v.y, g[e+1],
              fmaf(v.z, g[e+2], fmaf(v.w, g[e+3], acc))));
    }
    out[gbase + t] = acc;
}

// ---------------------------------------------------------------------------
extern "C" void kernel_launch(void* const* d_in, const int* in_sizes, int n_in,
                              void* d_out, int out_size)
{
    const float* x   = (const float*)d_in[0];
    const int*   ei  = (const int*)  d_in[1];
    const float* W1  = (const float*)d_in[2];
    const float* b1  = (const float*)d_in[3];
    const float* W2  = (const float*)d_in[4];
    const float* b2  = (const float*)d_in[5];
    const float* Wl1 = (const float*)d_in[6];
    const float* bl1 = (const float*)d_in[7];
    const float* Wl2 = (const float*)d_in[8];
    const float* bl2 = (const float*)d_in[9];
    const float* Wl3 = (const float*)d_in[10];
    const float* bl3 = (const float*)d_in[11];
    const float* Wl4 = (const float*)d_in[12];
    const float* bl4 = (const float*)d_in[13];

    const int B = in_sizes[0] / 56;          // 262144
    const int nblocks = B / GPB;             // 1024

    precompute_fused<<<32, 256>>>(W1, b1, W2, b2, Wl1, bl1, Wl2, bl2,
                                  Wl3, bl3, Wl4, bl4);

    cudaFuncSetAttribute(gnn_kernel,
                         cudaFuncAttributeMaxDynamicSharedMemorySize, SMEM_TOTAL);
    gnn_kernel<<<nblocks, TPB, SMEM_TOTAL>>>(x, ei, (float*)d_out);
}

// round 16
// speedup vs baseline: 1.1169x; 1.1169x over previous
#include <cuda_runtime.h>
#include <cstdint>

#define TPB 256
#define GPB 256  // graphs per block (== TPB, 1 thread per graph)

// Folded constants: v[4][16] (only k<14 used), s[4] @64..67, C @68
__device__ __align__(16) float g_const[80];
// Precompute scratch
__device__ __align__(16) float g_t1[256];
__device__ __align__(16) float g_t2[256];
__device__ __align__(16) float g_Ms[256];
__device__ __align__(16) float g_us[512];
// Grid-sync counters (reset at end of each precompute launch -> deterministic)
__device__ int g_syncc[4];

// ---------------------------------------------------------------------------
// Fused precompute: ONE kernel, 32 blocks x 256 threads, internal grid syncs.
// (unchanged structure from the 30.3us version; spins now use volatile loads)
// ---------------------------------------------------------------------------
__device__ __forceinline__ float dot256(const float4* wr, const float* vsm,
                                        int lane)
{
    float a = 0.f;
    #pragma unroll
    for (int i = 0; i < 2; ++i) {
        float4 w = wr[lane + 32 * i];
        int c = 4 * (lane + 32 * i);
        a = fmaf(w.x, vsm[c+0], fmaf(w.y, vsm[c+1],
            fmaf(w.z, vsm[c+2], fmaf(w.w, vsm[c+3], a))));
    }
    return a;
}

__global__ void __launch_bounds__(256) precompute_fused(
    const float* __restrict__ W1,  const float* __restrict__ b1,
    const float* __restrict__ W2,  const float* __restrict__ b2,
    const float* __restrict__ Wl1, const float* __restrict__ bl1,
    const float* __restrict__ Wl2, const float* __restrict__ bl2,
    const float* __restrict__ Wl3, const float* __restrict__ bl3,
    const float* __restrict__ Wl4, const float* __restrict__ bl4)
{
    __shared__ float w4s[256];
    __shared__ float tbuf[256];
    __shared__ __align__(16) float W2s[64 * 17 * 4];
    __shared__ __align__(16) float msbuf[64];
    __shared__ float part[256];
    __shared__ __align__(16) float us_s[512];

    const int t = threadIdx.x;
    const int b = blockIdx.x;
    const int row = b * 8 + (t >> 5);
    const int lane = t & 31;

    // ---- Stage 1: t1 = Wl3 @ w4 ----
    w4s[t] = Wl4[t];
    __syncthreads();
    {
        float a = dot256((const float4*)(Wl3 + row * 256), w4s, lane);
        #pragma unroll
        for (int o = 16; o; o >>= 1) a += __shfl_xor_sync(0xFFFFFFFFu, a, o);
        if (lane == 0) g_t1[row] = a;
    }
    __syncthreads();
    if (t == 0) {
        __threadfence(); atomicAdd(&g_syncc[0], 1);
        while (*(volatile int*)&g_syncc[0] < 32) {}
        __threadfence();
    }
    __syncthreads();

    // ---- Stage 2: t2 = Wl2 @ t1 ----
    tbuf[t] = g_t1[t];
    __syncthreads();
    {
        float a = dot256((const float4*)(Wl2 + row * 256), tbuf, lane);
        #pragma unroll
        for (int o = 16; o; o >>= 1) a += __shfl_xor_sync(0xFFFFFFFFu, a, o);
        if (lane == 0) g_t2[row] = a;
    }
    __syncthreads();
    if (t == 0) {
        __threadfence(); atomicAdd(&g_syncc[1], 1);
        while (*(volatile int*)&g_syncc[1] < 32) {}
        __threadfence();
    }
    __syncthreads();

    // ---- Stage 3: Ms = Wl1 @ t2 + Wl1 @ w4 + w4 ----
    tbuf[t] = g_t2[t];
    __syncthreads();
    {
        const float4* wr = (const float4*)(Wl1 + row * 256);
        float a1 = 0.f, a2 = 0.f;
        #pragma unroll
        for (int i = 0; i < 2; ++i) {
            float4 w = wr[lane + 32 * i];
            int c = 4 * (lane + 32 * i);
            a1 = fmaf(w.x, tbuf[c+0], fmaf(w.y, tbuf[c+1],
                 fmaf(w.z, tbuf[c+2], fmaf(w.w, tbuf[c+3], a1))));
            a2 = fmaf(w.x, w4s[c+0], fmaf(w.y, w4s[c+1],
                 fmaf(w.z, w4s[c+2], fmaf(w.w, w4s[c+3], a2))));
        }
        #pragma unroll
        for (int o = 16; o; o >>= 1) {
            a1 += __shfl_xor_sync(0xFFFFFFFFu, a1, o);
            a2 += __shfl_xor_sync(0xFFFFFFFFu, a2, o);
        }
        if (lane == 0) g_Ms[row] = a1 + a2 + w4s[row];
    }
    __syncthreads();
    if (t == 0) { __threadfence(); atomicAdd(&g_syncc[2], 1); }
    if (b >= 8) return;                   // arrive-and-exit, never spin
    if (t == 0) {
        while (*(volatile int*)&g_syncc[2] < 32) {}
        __threadfence();
    }
    __syncthreads();

    // ---- Stage 4 (blocks 0-7): u ----
    {
        const int n = b >> 1;
        const int chalf = (b & 1) * 64;
        float4* W2s4 = (float4*)W2s;
        const float4* src = ((const float4*)W2) + chalf * 16;
        #pragma unroll
        for (int i2 = 0; i2 < 4; ++i2) {
            int idx = t + 256 * i2;
            int c = idx >> 4, i = idx & 15;
            W2s4[c * 17 + i] = src[idx];
        }
        if (t < 16) ((float4*)msbuf)[t] = ((const float4*)g_Ms)[n * 16 + t];
        __syncthreads();

        const int q = t >> 6, c = t & 63;
        const float4* ms4 = (const float4*)msbuf;
        float a = 0.f;
        #pragma unroll
        for (int i = 0; i < 4; ++i) {
            float4 w = W2s4[c * 17 + q * 4 + i];
            float4 m = ms4[q * 4 + i];
            a = fmaf(w.x, m.x, fmaf(w.y, m.y, fmaf(w.z, m.z, fmaf(w.w, m.w, a))));
        }
        part[t] = a;
        __syncthreads();
        if (t < 64)
            g_us[n * 128 + chalf + t] =
                part[t] + part[t + 64] + part[t + 128] + part[t + 192];
    }
    __syncthreads();
    if (t == 0) { __threadfence(); atomicAdd(&g_syncc[3], 1); }
    if (b > 0) return;                    // arrive-and-exit
    if (t == 0) {
        while (*(volatile int*)&g_syncc[3] < 8) {}
        __threadfence();
    }
    __syncthreads();

    // ---- Stage 5 (block 0): v[n][k], s[n], C ----
    {
        float pc = bl1[t]*g_t2[t] + bl2[t]*g_t1[t]
                 + (bl3[t]+bl1[t])*Wl4[t] + b2[t & 63]*g_Ms[t];
        part[t] = pc;
        us_s[t] = g_us[t];
        us_s[t + 256] = g_us[t + 256];
        __syncthreads();

        if (t < 224) {                    // v[n][k]: 4 threads per output
            int o = t >> 2, q = t & 3;
            int n = o / 14, k = o - 14 * n;
            const float4* wr = (const float4*)(W1 + k * 128);
            const float4* ur = ((const float4*)us_s) + n * 32;
            float a = 0.f;
            #pragma unroll
            for (int i = 0; i < 8; ++i) {
                float4 w = wr[q * 8 + i];
                float4 u = ur[q * 8 + i];
                a = fmaf(w.x, u.x, fmaf(w.y, u.y,
                    fmaf(w.z, u.z, fmaf(w.w, u.w, a))));
            }
            a += __shfl_xor_sync(0xFFFFFFFFu, a, 1);
            a += __shfl_xor_sync(0xFFFFFFFFu, a, 2);
            if (q == 0) g_const[n * 16 + k] = a;
        } else {                          // s_n: 8 threads per n
            int o2 = t - 224;
            int n = o2 >> 3, q = o2 & 7;
            float a = 0.f;
            #pragma unroll
            for (int i = 0; i < 16; ++i)
                a = fmaf(b1[q * 16 + i], us_s[n * 128 + q * 16 + i], a);
            a += __shfl_xor_sync(0xFFFFFFFFu, a, 1);
            a += __shfl_xor_sync(0xFFFFFFFFu, a, 2);
            a += __shfl_xor_sync(0xFFFFFFFFu, a, 4);
            if (q == 0) g_const[64 + n] = a;
        }
        __syncthreads();
        #pragma unroll
        for (int s = 128; s > 0; s >>= 1) {
            if (t < s) part[t] += part[t + s];
            __syncthreads();
        }
        if (t == 0) g_const[68] = part[0] + bl4[0];
    }
    __syncthreads();
    if (t == 0) {
        g_syncc[0] = 0; g_syncc[1] = 0; g_syncc[2] = 0; g_syncc[3] = 0;
        __threadfence();
    }
}

// Exactly-rounded 1/sqrt(n) for n = 0..15 (deg in [1,13])
__constant__ float c_rsq[16] = {
    0.0f, 1.0f, 0.70710678118654752f, 0.57735026918962576f,
    0.5f, 0.44721359549995794f, 0.40824829046386302f, 0.37796447300922723f,
    0.35355339059327376f, 0.33333333333333333f, 0.31622776601683794f,
    0.30151134457776363f, 0.28867513459481288f, 0.27735009811261457f,
    0.26726124191242438f, 0.25819888974716110f
};

// ---------------------------------------------------------------------------
// Main kernel v3: ONE barrier.
//   - x staged via cp.async.cg (16B), coalesced src, odd-stride smem dst
//   - edges loaded per-thread directly (6 x int4; warp hits 24 L1 lines,
//     fully consumed -> no DRAM waste, no smem, no extra barriers)
//   - A/A2/rowsums built from registers while cp.async lands
//   - cs-dependent math strictly after the single __syncthreads
// smem: xs4 61440B + cs 320B = 61760 -> 3 blocks/SM.
// ---------------------------------------------------------------------------
#define SMEM_CS 61440
#define SMEM_TOTAL 61760

__global__ void __launch_bounds__(TPB, 3) gnn_kernel(
    const float* __restrict__ x, const int* __restrict__ ei,
    float* __restrict__ out)
{
    extern __shared__ unsigned char smem[];
    float4* xs4 = (float4*)smem;
    float*  cs  = (float*)(smem + SMEM_CS);

    const int t = threadIdx.x;
    const long long gbase = (long long)blockIdx.x * GPB;

    // ---- issue x staging: 14 cp.async.cg per thread, coalesced ----
    const float4* xg = (const float4*)(x + gbase * 56);
    uint32_t xs_base = (uint32_t)__cvta_generic_to_shared(xs4);
    #pragma unroll
    for (int j0 = 0; j0 < 14; ++j0) {
        int i4 = t + j0 * 256;
        int g = i4 / 14;
        int j = i4 - g * 14;
        uint32_t dst = xs_base + (uint32_t)(g * 15 + j) * 16u;
        asm volatile("cp.async.cg.shared.global [%0], [%1], 16;\n"
                     :: "r"(dst), "l"(xg + i4));
    }
    asm volatile("cp.async.commit_group;\n");

    // ---- edges: direct per-thread loads (96B/graph, int4-aligned) ----
    const int4* ep = (const int4*)(ei + (gbase + t) * 24);
    int4 e0 = ep[0], e1 = ep[1], e2 = ep[2];
    int4 e3 = ep[3], e4 = ep[4], e5 = ep[5];

    // ---- cs: 80 floats via t<80 (visible after the single sync) ----
    if (t < 80) cs[t] = g_const[t];

    // ---- nibble-packed edge counting (src = e0..e2, dst = e3..e5) ----
    int srcv[12] = {e0.x,e0.y,e0.z,e0.w, e1.x,e1.y,e1.z,e1.w,
                    e2.x,e2.y,e2.z,e2.w};
    int dstv[12] = {e3.x,e3.y,e3.z,e3.w, e4.x,e4.y,e4.z,e4.w,
                    e5.x,e5.y,e5.z,e5.w};
    unsigned long long accm = 0ull;
    #pragma unroll
    for (int e = 0; e < 12; ++e)
        accm += 1ull << (((dstv[e] << 2) + srcv[e]) << 2);

    float dinv[4];
    #pragma unroll
    for (int n = 0; n < 4; ++n) {
        unsigned int rown = (unsigned int)(accm >> (16 * n)) & 0xFFFFu;
        int deg = 1 + (rown & 15) + ((rown >> 4) & 15)
                    + ((rown >> 8) & 15) + ((rown >> 12) & 15);
        dinv[n] = c_rsq[deg];
    }

    float A[16];
    #pragma unroll
    for (int n = 0; n < 4; ++n) {
        #pragma unroll
        for (int m = 0; m < 4; ++m) {
            int cnt = (int)((accm >> (4 * (n * 4 + m))) & 15ull) + (n == m);
            A[n * 4 + m] = dinv[n] * dinv[m] * (float)cnt;
        }
    }

    float rowsum[4];
    #pragma unroll
    for (int n = 0; n < 4; ++n)
        rowsum[n] = A[n*4] + A[n*4+1] + A[n*4+2] + A[n*4+3];

    float A2[16];
    #pragma unroll
    for (int n = 0; n < 4; ++n) {
        #pragma unroll
        for (int m = 0; m < 4; ++m) {
            A2[n*4+m] = fmaf(A[n*4+0], A[0*4+m],
                        fmaf(A[n*4+1], A[1*4+m],
                        fmaf(A[n*4+2], A[2*4+m], A[n*4+3] * A[3*4+m])));
        }
    }

    // ---- single wait + barrier: x in smem, cs visible ----
    asm volatile("cp.async.wait_group 0;\n");
    __syncthreads();

    // ---- cs-dependent scalars (post-sync) ----
    float acc = cs[68];
    #pragma unroll
    for (int n = 0; n < 4; ++n)
        acc = fmaf(rowsum[n], cs[64 + n], acc);

    float g[56];
    #pragma unroll
    for (int e = 0; e < 56; ++e) {
        const int m = e / 14, k = e - 14 * m;
        g[e] = fmaf(A2[0*4+m], cs[0*16+k],
               fmaf(A2[1*4+m], cs[1*16+k],
               fmaf(A2[2*4+m], cs[2*16+k], A2[3*4+m] * cs[3*16+k])));
    }

    // ---- stream x: 14 conflict-free LDS.128, consume directly ----
    #pragma unroll
    for (int j = 0; j < 14; ++j) {
        float4 v = xs4[t * 15 + j];
        const int e = 4 * j;
        acc = fmaf(v.x, g[e+0], fmaf(v.y, g[e+1],
              fmaf(v.z, g[e+2], fmaf(v.w, g[e+3], acc))));
    }
    out[gbase + t] = acc;
}

// ---------------------------------------------------------------------------
extern "C" void kernel_launch(void* const* d_in, const int* in_sizes, int n_in,
                              void* d_out, int out_size)
{
    const float* x   = (const float*)d_in[0];
    const int*   ei  = (const int*)  d_in[1];
    const float* W1  = (const float*)d_in[2];
    const float* b1  = (const float*)d_in[3];
    const float* W2  = (const float*)d_in[4];
    const float* b2  = (const float*)d_in[5];
    const float* Wl1 = (const float*)d_in[6];
    const float* bl1 = (const float*)d_in[7];
    const float* Wl2 = (const float*)d_in[8];
    const float* bl2 = (const float*)d_in[9];
    const float* Wl3 = (const float*)d_in[10];
    const float* bl3 = (const float*)d_in[11];
    const float* Wl4 = (const float*)d_in[12];
    const float* bl4 = (const float*)d_in[13];

    const int B = in_sizes[0] / 56;          // 262144
    const int nblocks = B / GPB;             // 1024

    precompute_fused<<<32, 256>>>(W1, b1, W2, b2, Wl1, bl1, Wl2, bl2,
                                  Wl3, bl3, Wl4, bl4);

    cudaFuncSetAttribute(gnn_kernel,
                         cudaFuncAttributeMaxDynamicSharedMemorySize, SMEM_TOTAL);
    gnn_kernel<<<nblocks, TPB, SMEM_TOTAL>>>(x, ei, (float*)d_out);
}